// round 2
// baseline (speedup 1.0000x reference)
#include <cuda_runtime.h>
#include <math.h>

// CRF log-likelihood. N=2048, T=200, L=129, fp32, scalar output.
//
// Forward recurrence in normalized exp-domain:
//   keep p[j] (unnormalized probabilities) + c2 (accumulated log2 scale)
//   s[j] = sum_i p[i] * E[i][j],  E = exp(transitions)  (precomputed)
//   u[j] = s[j] * exp(logit_t[j])
//   every 4 steps: S = sum u; c2 += log2(S); p = u/S   (else p = u)
//   log_den = ln2 * (c2 + log2(sum_j p[j]*exp(end[j])))
// => L exps/step instead of L^2; the L x L work is pure fp32 FFMA from smem.
//
// Sequences counting-sorted by length desc, paired 2-per-warp (adjacent
// lengths => ~no lockstep waste), snake-scheduled over 296 CTAs x 4 warps
// (2 CTAs/SM) for load balance. Per-seq results are deterministic regardless
// of warp assignment; final reduction is fixed-order in double.

#define NN 2048
#define TT 200
#define LL 129
#define LPAD 132          // E row stride (floats), keeps rows 16B aligned
#define PAIRS 1024
#define FWD_CTAS 296
#define FWD_WARPS 4
#define PSTR 136          // per-seq p buffer stride (floats), 16B aligned

__device__ __align__(16) float g_E[LL * LPAD];   // exp(transitions), padded
__device__ __align__(16) float g_Eend[LPAD];     // exp(end_transitions)
__device__ int   g_order[NN];
__device__ float g_num[NN];
__device__ float g_den[NN];

__device__ __forceinline__ float ex2f(float x){ float r; asm("ex2.approx.ftz.f32 %0, %1;":"=f"(r):"f"(x)); return r; }
__device__ __forceinline__ float lg2f(float x){ float r; asm("lg2.approx.ftz.f32 %0, %1;":"=f"(r):"f"(x)); return r; }
__device__ __forceinline__ float rcpf(float x){ float r; asm("rcp.approx.ftz.f32 %0, %1;":"=f"(r):"f"(x)); return r; }

#define LOG2E 1.4426950408889634f
#define LN2F  0.6931471805599453f

// ---------------------------------------------------------------------------
// Prep: E = exp(transitions) (col-padded with zeros), Eend = exp(end)
// ---------------------------------------------------------------------------
__global__ void prep_kernel(const float* __restrict__ trans,
                            const float* __restrict__ endt) {
    int idx = blockIdx.x * blockDim.x + threadIdx.x;
    if (idx < LL * LPAD) {
        int i = idx / LPAD, j = idx - i * LPAD;
        g_E[idx] = (j < LL) ? ex2f(trans[i * LL + j] * LOG2E) : 0.0f;
    }
    if (idx < LPAD) g_Eend[idx] = (idx < LL) ? ex2f(endt[idx] * LOG2E) : 0.0f;
}

// ---------------------------------------------------------------------------
// Counting sort by length, descending. Order within equal lengths is
// nondeterministic (atomics) but per-seq results don't depend on assignment.
// ---------------------------------------------------------------------------
__global__ void sort_kernel(const int* __restrict__ lengths) {
    __shared__ int hist[256];
    int tid = threadIdx.x;
    for (int k = tid; k < 256; k += blockDim.x) hist[k] = 0;
    __syncthreads();
    for (int n = tid; n < NN; n += blockDim.x) atomicAdd(&hist[lengths[n]], 1);
    __syncthreads();
    if (tid == 0) {
        int run = 0;
        for (int l = 200; l >= 1; --l) { int c = hist[l]; hist[l] = run; run += c; }
    }
    __syncthreads();
    for (int n = tid; n < NN; n += blockDim.x) {
        int pos = atomicAdd(&hist[lengths[n]], 1);
        g_order[pos] = n;
    }
}

// ---------------------------------------------------------------------------
// Numerator: one warp per sequence.
//   num = start[g0] + sum_{t<len} score[n,t,g_t]
//       + sum_{1<=t<len} trans[g_{t-1}, g_t] + end[g_{len-1}]
// ---------------------------------------------------------------------------
__global__ void num_kernel(const float* __restrict__ score,
                           const float* __restrict__ trans,
                           const float* __restrict__ startt,
                           const float* __restrict__ endt,
                           const int* __restrict__ gold,
                           const int* __restrict__ lengths) {
    int w    = (blockIdx.x * blockDim.x + threadIdx.x) >> 5;
    int lane = threadIdx.x & 31;
    if (w >= NN) return;
    const int* g = gold + w * TT;
    int len = lengths[w];
    const float* sc = score + (size_t)w * TT * LL;
    float acc = 0.0f;
    for (int t = lane; t < len; t += 32) {
        int gt = __ldg(&g[t]);
        acc += __ldg(&sc[t * LL + gt]);
        if (t >= 1) {
            int gp = __ldg(&g[t - 1]);
            acc += __ldg(&trans[gp * LL + gt]);
        }
    }
    #pragma unroll
    for (int o = 16; o; o >>= 1) acc += __shfl_xor_sync(0xffffffffu, acc, o);
    if (lane == 0) {
        g_num[w] = acc + startt[g[0]] + endt[g[len - 1]];
    }
}

// ---------------------------------------------------------------------------
// Forward kernel: 4 warps/CTA, 2 sequences/warp, E resident in smem.
// Lane l owns output columns j0=4l..4l+3 (LDS.128 of E row), column 128 is
// computed i-parallel + warp butterfly. p broadcasts amortized 4-wide (16B).
// ---------------------------------------------------------------------------
__global__ void __launch_bounds__(FWD_WARPS * 32, 2)
fwd_kernel(const float* __restrict__ score,
           const float* __restrict__ startt,
           const int* __restrict__ lengths) {
    extern __shared__ float sm[];
    float* Es   = sm;                  // LL*LPAD
    float* Ec   = Es + LL * LPAD;      // LPAD   (E column 128)
    float* Een  = Ec + LPAD;           // LPAD   (exp(end))
    float* pbuf = Een + LPAD;          // FWD_WARPS * 2 * PSTR

    int tid = threadIdx.x;
    for (int k = tid; k < LL * LPAD; k += blockDim.x) Es[k] = g_E[k];
    if (tid < LPAD) {
        Ec[tid]  = (tid < LL) ? g_E[tid * LPAD + 128] : 0.0f;
        Een[tid] = g_Eend[tid];
    }
    __syncthreads();

    int w = tid >> 5, lane = tid & 31;
    // snake schedule: pass = warp id, forward/backward alternating over CTAs
    int r = (w & 1) ? (w * FWD_CTAS + (FWD_CTAS - 1 - (int)blockIdx.x))
                    : (w * FWD_CTAS + (int)blockIdx.x);
    if (r >= PAIRS) return;

    int nA = g_order[2 * r + 0];
    int nB = g_order[2 * r + 1];
    int lenA = lengths[nA], lenB = lengths[nB];
    int tmax = lenA > lenB ? lenA : lenB;

    float* pA = pbuf + w * (2 * PSTR);
    float* pB = pA + PSTR;
    const float* scA = score + (size_t)nA * TT * LL;
    const float* scB = score + (size_t)nB * TT * LL;
    int j0 = lane * 4;

    // ---- init: p0[j] = exp(start[j] + score[n,0,j]), c2 = 0
    {
        float4 s4 = *(const float4*)&startt[j0];
        float4 a4 = *(const float4*)&scA[j0];   // row t=0 is 16B aligned
        float4 b4 = *(const float4*)&scB[j0];
        float4 pa, pb;
        pa.x = ex2f((s4.x + a4.x) * LOG2E); pa.y = ex2f((s4.y + a4.y) * LOG2E);
        pa.z = ex2f((s4.z + a4.z) * LOG2E); pa.w = ex2f((s4.w + a4.w) * LOG2E);
        pb.x = ex2f((s4.x + b4.x) * LOG2E); pb.y = ex2f((s4.y + b4.y) * LOG2E);
        pb.z = ex2f((s4.z + b4.z) * LOG2E); pb.w = ex2f((s4.w + b4.w) * LOG2E);
        *(float4*)&pA[j0] = pa;
        *(float4*)&pB[j0] = pb;
        if (lane == 0) {
            float st128 = startt[128];
            pA[128] = ex2f((st128 + scA[128]) * LOG2E);
            pB[128] = ex2f((st128 + scB[128]) * LOG2E);
        }
    }
    float c2A = 0.0f, c2B = 0.0f;
    __syncwarp();

    const float* erow = Es + j0;

    for (int t = 1; t < tmax; ++t) {
        float sA0 = 0.f, sA1 = 0.f, sA2 = 0.f, sA3 = 0.f;
        float sB0 = 0.f, sB1 = 0.f, sB2 = 0.f, sB3 = 0.f;

        // ---- matvec over i = 0..127, p broadcast in 16B chunks
        #pragma unroll 4
        for (int c = 0; c < 32; ++c) {
            float4 pa4 = *(const float4*)&pA[c * 4];
            float4 pb4 = *(const float4*)&pB[c * 4];
            float4 e0 = *(const float4*)&erow[(c * 4 + 0) * LPAD];
            sA0 += e0.x * pa4.x; sA1 += e0.y * pa4.x; sA2 += e0.z * pa4.x; sA3 += e0.w * pa4.x;
            sB0 += e0.x * pb4.x; sB1 += e0.y * pb4.x; sB2 += e0.z * pb4.x; sB3 += e0.w * pb4.x;
            float4 e1 = *(const float4*)&erow[(c * 4 + 1) * LPAD];
            sA0 += e1.x * pa4.y; sA1 += e1.y * pa4.y; sA2 += e1.z * pa4.y; sA3 += e1.w * pa4.y;
            sB0 += e1.x * pb4.y; sB1 += e1.y * pb4.y; sB2 += e1.z * pb4.y; sB3 += e1.w * pb4.y;
            float4 e2 = *(const float4*)&erow[(c * 4 + 2) * LPAD];
            sA0 += e2.x * pa4.z; sA1 += e2.y * pa4.z; sA2 += e2.z * pa4.z; sA3 += e2.w * pa4.z;
            sB0 += e2.x * pb4.z; sB1 += e2.y * pb4.z; sB2 += e2.z * pb4.z; sB3 += e2.w * pb4.z;
            float4 e3 = *(const float4*)&erow[(c * 4 + 3) * LPAD];
            sA0 += e3.x * pa4.w; sA1 += e3.y * pa4.w; sA2 += e3.z * pa4.w; sA3 += e3.w * pa4.w;
            sB0 += e3.x * pb4.w; sB1 += e3.y * pb4.w; sB2 += e3.z * pb4.w; sB3 += e3.w * pb4.w;
        }
        { // i = 128
            float4 e = *(const float4*)&erow[128 * LPAD];
            float pa = pA[128], pb = pB[128];
            sA0 += e.x * pa; sA1 += e.y * pa; sA2 += e.z * pa; sA3 += e.w * pa;
            sB0 += e.x * pb; sB1 += e.y * pb; sB2 += e.z * pb; sB3 += e.w * pb;
        }

        // ---- output column j = 128: i-parallel partials + butterfly
        float s128a, s128b;
        {
            float e0c = Ec[lane], e1c = Ec[lane + 32], e2c = Ec[lane + 64], e3c = Ec[lane + 96];
            s128a = e0c * pA[lane] + e1c * pA[lane + 32] + e2c * pA[lane + 64] + e3c * pA[lane + 96];
            s128b = e0c * pB[lane] + e1c * pB[lane + 32] + e2c * pB[lane + 64] + e3c * pB[lane + 96];
            if (lane == 0) { s128a += Ec[128] * pA[128]; s128b += Ec[128] * pB[128]; }
            #pragma unroll
            for (int o = 16; o; o >>= 1) {
                s128a += __shfl_xor_sync(0xffffffffu, s128a, o);
                s128b += __shfl_xor_sync(0xffffffffu, s128b, o);
            }
        }

        // ---- emissions (rows t>=1 not 16B aligned -> scalar loads)
        const float* rA = scA + t * LL;
        const float* rB = scB + t * LL;
        float uA0 = sA0 * ex2f(__ldg(&rA[j0 + 0]) * LOG2E);
        float uA1 = sA1 * ex2f(__ldg(&rA[j0 + 1]) * LOG2E);
        float uA2 = sA2 * ex2f(__ldg(&rA[j0 + 2]) * LOG2E);
        float uA3 = sA3 * ex2f(__ldg(&rA[j0 + 3]) * LOG2E);
        float uB0 = sB0 * ex2f(__ldg(&rB[j0 + 0]) * LOG2E);
        float uB1 = sB1 * ex2f(__ldg(&rB[j0 + 1]) * LOG2E);
        float uB2 = sB2 * ex2f(__ldg(&rB[j0 + 2]) * LOG2E);
        float uB3 = sB3 * ex2f(__ldg(&rB[j0 + 3]) * LOG2E);
        float uA128 = s128a * ex2f(__ldg(&rA[128]) * LOG2E);
        float uB128 = s128b * ex2f(__ldg(&rB[128]) * LOG2E);

        bool aA = t < lenA, aB = t < lenB;
        __syncwarp();   // all reads of old p done before any writes

        if ((t & 3) == 0) {
            // renormalize
            float tA = uA0 + uA1 + uA2 + uA3; if (lane == 0) tA += uA128;
            float tB = uB0 + uB1 + uB2 + uB3; if (lane == 0) tB += uB128;
            #pragma unroll
            for (int o = 16; o; o >>= 1) {
                tA += __shfl_xor_sync(0xffffffffu, tA, o);
                tB += __shfl_xor_sync(0xffffffffu, tB, o);
            }
            if (aA) {
                float s = rcpf(tA); c2A += lg2f(tA);
                *(float4*)&pA[j0] = make_float4(uA0 * s, uA1 * s, uA2 * s, uA3 * s);
                if (lane == 0) pA[128] = uA128 * s;
            }
            if (aB) {
                float s = rcpf(tB); c2B += lg2f(tB);
                *(float4*)&pB[j0] = make_float4(uB0 * s, uB1 * s, uB2 * s, uB3 * s);
                if (lane == 0) pB[128] = uB128 * s;
            }
        } else {
            if (aA) {
                *(float4*)&pA[j0] = make_float4(uA0, uA1, uA2, uA3);
                if (lane == 0) pA[128] = uA128;
            }
            if (aB) {
                *(float4*)&pB[j0] = make_float4(uB0, uB1, uB2, uB3);
                if (lane == 0) pB[128] = uB128;
            }
        }
        __syncwarp();   // writes visible before next iteration's reads
    }

    // ---- finalize: log_den = ln2 * (c2 + log2(sum_j p[j]*Eend[j]))
    {
        float4 ee  = *(const float4*)&Een[j0];
        float4 pa4 = *(const float4*)&pA[j0];
        float4 pb4 = *(const float4*)&pB[j0];
        float vA = ee.x * pa4.x + ee.y * pa4.y + ee.z * pa4.z + ee.w * pa4.w;
        float vB = ee.x * pb4.x + ee.y * pb4.y + ee.z * pb4.z + ee.w * pb4.w;
        if (lane == 0) { vA += Een[128] * pA[128]; vB += Een[128] * pB[128]; }
        #pragma unroll
        for (int o = 16; o; o >>= 1) {
            vA += __shfl_xor_sync(0xffffffffu, vA, o);
            vB += __shfl_xor_sync(0xffffffffu, vB, o);
        }
        if (lane == 0) {
            g_den[nA] = LN2F * (c2A + lg2f(vA));
            g_den[nB] = LN2F * (c2B + lg2f(vB));
        }
    }
}

// ---------------------------------------------------------------------------
// Deterministic fixed-order reduction in double.
// ---------------------------------------------------------------------------
__global__ void red_kernel(float* __restrict__ out) {
    __shared__ double smd[1024];
    int tid = threadIdx.x;
    double d = (double)(g_num[tid] - g_den[tid]) +
               (double)(g_num[tid + 1024] - g_den[tid + 1024]);
    smd[tid] = d;
    __syncthreads();
    #pragma unroll
    for (int s = 512; s > 0; s >>= 1) {
        if (tid < s) smd[tid] += smd[tid + s];
        __syncthreads();
    }
    if (tid == 0) out[0] = (float)smd[0];
}

// ---------------------------------------------------------------------------
extern "C" void kernel_launch(void* const* d_in, const int* in_sizes, int n_in,
                              void* d_out, int out_size) {
    const float* score  = (const float*)d_in[0];
    const float* trans  = (const float*)d_in[1];
    const float* startt = (const float*)d_in[2];
    const float* endt   = (const float*)d_in[3];
    const int*   gold   = (const int*)d_in[4];
    const int*   lengths= (const int*)d_in[5];
    float* out = (float*)d_out;

    prep_kernel<<<(LL * LPAD + 255) / 256, 256>>>(trans, endt);
    sort_kernel<<<1, 256>>>(lengths);
    num_kernel<<<256, 256>>>(score, trans, startt, endt, gold, lengths);

    size_t smem = (size_t)(LL * LPAD + 2 * LPAD + FWD_WARPS * 2 * PSTR) * sizeof(float);
    cudaFuncSetAttribute(fwd_kernel, cudaFuncAttributeMaxDynamicSharedMemorySize, (int)smem);
    fwd_kernel<<<FWD_CTAS, FWD_WARPS * 32, smem>>>(score, startt, lengths);

    red_kernel<<<1, 1024>>>(out);
}